// round 5
// baseline (speedup 1.0000x reference)
#include <cuda_runtime.h>

// Shapes fixed by the dataset
#define NN   8192
#define D    128
#define PP   256
#define KK   256
#define DEGN 32
#define FFN  16
#define TEMP_INV (1.0f/0.07f)
#define NB_TERM (PP * 4)          // 4 quarter-blocks per p, 8 warps each
#define NB_NEG  (KK / 8)          // 8 negatives per block, one per warp
#define GRID    (NB_TERM + NB_NEG)

// Scratch (no allocations allowed)
__device__ float4 g_part4[PP * 4];   // [p][quarter] = {Sw1, Sw1mu1, Sw2, Sw2mu2}
__device__ float  g_pos[PP];
__device__ float  g_core[PP];
__device__ float  g_neg[KK];
__device__ unsigned int g_ctr;       // zero-init; last block resets each launch

__device__ __forceinline__ float warpSum(float v) {
#pragma unroll
    for (int o = 16; o; o >>= 1) v += __shfl_xor_sync(0xffffffffu, v, o);
    return v;
}
// sums independently within each 16-lane half
__device__ __forceinline__ float halfSum(float v) {
#pragma unroll
    for (int o = 8; o; o >>= 1) v += __shfl_xor_sync(0xffffffffu, v, o);
    return v;
}
__device__ __forceinline__ float dot4(float4 a, float4 b) {
    return a.x*b.x + a.y*b.y + a.z*b.z + a.w*b.w;
}
// release-scoped counter increment: orders prior global stores without CCTL.IVALL
__device__ __forceinline__ unsigned int ctrAddRelease(unsigned int* p) {
    unsigned int old;
    asm volatile("atom.add.release.gpu.global.u32 %0, [%1], 1;"
                 : "=r"(old) : "l"(p) : "memory");
    return old;
}

// ---------------------------------------------------------------------------
// Single fused kernel. Term blocks: b < NB_TERM, p = b>>2, quarter = b&3,
// warp w handles j = quarter*8 + w, fully warp-local (broadcast loads).
// Neg blocks: one negative per warp. Last block folds the scalar reduction.
// ---------------------------------------------------------------------------
__global__ void __launch_bounds__(256)
k_all(const float* __restrict__ z,
      const float* __restrict__ edge_times,
      const float* __restrict__ cur_t,
      const float* __restrict__ core,
      const float* __restrict__ omega,
      const float* __restrict__ phi,
      const int*   __restrict__ qidx,
      const int*   __restrict__ neg_idxs,
      const int*   __restrict__ nbr_idxs,
      const int*   __restrict__ neighbors,
      float* __restrict__ out)
{
    __shared__ float  s_acc[32];      // 8 warps x {w1, w1mu1, w2, w2mu2}
    __shared__ float  s_fr[4][8];
    __shared__ unsigned int s_islast;

    const int tid  = threadIdx.x;
    const int lane = tid & 31, warp = tid >> 5;
    const int b    = blockIdx.x;
    const int q    = qidx[0];            // broadcast load
    const float ct = cur_t[0];

    if (b < NB_TERM) {
        const int p   = b >> 2;
        const int qtr = b & 3;
        const int j   = qtr * 8 + warp;
        const int nbp = nbr_idxs[p];                       // broadcast

        // depth-3 load chains (two independent), all broadcast within warp
        const int nqj  = neighbors[q   * DEGN + j];
        const int idx2 = neighbors[nbp * DEGN + j];
        const float etq = edge_times[(size_t)q   * NN + nqj];
        const float ety = edge_times[(size_t)nbp * NN + idx2];

        const float4 x  = ((const float4*)(z + (size_t)nqj  * D))[lane];
        const float4 r  = ((const float4*)(z + (size_t)idx2 * D))[lane];
        const float4 zq = ((const float4*)(z + (size_t)q    * D))[lane];
        const float4 vb = ((const float4*)(z + (size_t)nbp  * D))[lane];

        // time encodings: lanes 0-15 -> query side, lanes 16-31 -> neighbor side
        const int   f  = lane & 15;
        const float dt = (lane < 16) ? (ct - etq) : (ct - ety);
        float c = (f == 0) ? (omega[0] * dt + phi[0])
                           : __sinf(omega[f] * dt + phi[f]);

        // independent butterflies (ILP-overlapped)
        float ssx = warpSum(dot4(x, x));
        float ssr = warpSum(dot4(r, r));
        float ssq = warpSum(dot4(zq, zq));
        float ssb = warpSum(dot4(vb, vb));
        float d1  = warpSum(dot4(x, vb));
        float d2  = warpSum(dot4(r, zq));
        float hc  = halfSum(c);
        const float te1 = __shfl_sync(0xffffffffu, hc, 0);
        const float te2 = __shfl_sync(0xffffffffu, hc, 16);

        const float mu1 = 2.f * d1 * rsqrtf(ssx * ssb) - 2.f;
        const float w1  = __expf(mu1 * TEMP_INV - te1);
        const float mu2 = 2.f * d2 * rsqrtf(ssr * ssq) - 2.f;
        const float w2  = __expf(mu2 * TEMP_INV - te2);

        if (lane < 4) {
            float v4 = (lane == 0) ? w1 : (lane == 1) ? w1 * mu1
                     : (lane == 2) ? w2 : w2 * mu2;
            s_acc[warp * 4 + lane] = v4;
        }

        // quarter 0, warp 0 additionally emits pos-loss and core term for p
        if (qtr == 0 && warp == 0) {
            float dqb = warpSum(dot4(vb, zq));
            if (lane == 0) {
                float muxy = 2.f * dqb * rsqrtf(ssb * ssq) - 2.f;
                float sgm  = 1.f / (1.f + __expf(-muxy));
                g_pos[p] = -__logf(sgm + 1e-8f);
                float cd = core[nbp] - core[q];
                g_core[p] = cd * cd;
            }
        }
        __syncthreads();

        if (warp == 0) {
            // segmented cross-warp butterfly: sum over warps (stride-4 groups)
            float v = s_acc[lane];
            v += __shfl_xor_sync(0xffffffffu, v, 16);
            v += __shfl_xor_sync(0xffffffffu, v, 8);
            v += __shfl_xor_sync(0xffffffffu, v, 4);
            if (lane < 4)
                ((float*)&g_part4[p * 4 + qtr])[lane] = v;
        }
    } else {
        // negative blocks: warp w handles negative k
        const int k  = (b - NB_TERM) * 8 + warp;
        const int nk = neg_idxs[k];                        // broadcast
        const float4 v  = ((const float4*)(z + (size_t)nk * D))[lane];
        const float4 zq = ((const float4*)(z + (size_t)q  * D))[lane];
        float ssv = warpSum(dot4(v, v));
        float ssq = warpSum(dot4(zq, zq));
        float dv  = warpSum(dot4(v, zq));
        if (lane == 0) {
            float mu  = 2.f * dv * rsqrtf(ssv * ssq) - 2.f;
            float sgm = 1.f / (1.f + __expf(-mu));
            g_neg[k] = -__logf(1.f - sgm + 1e-8f);
        }
    }

    // ---- last-block final reduction (release/acquire-free via L2 reads) ----
    __syncthreads();
    if (tid == 0) {
        unsigned int t = ctrAddRelease(&g_ctr);
        s_islast = (t == (unsigned int)(GRID - 1));
    }
    __syncthreads();
    if (s_islast) {
        // thread tid owns p = tid (and neg k = tid); read straight from L2
        const float4* gp = g_part4 + tid * 4;
        float4 q0 = __ldcg(gp + 0);
        float4 q1 = __ldcg(gp + 1);
        float4 q2 = __ldcg(gp + 2);
        float4 q3 = __ldcg(gp + 3);
        float W1  = q0.x + q1.x + q2.x + q3.x;
        float WM1 = q0.y + q1.y + q2.y + q3.y;
        float W2  = q0.z + q1.z + q2.z + q3.z;
        float WM2 = q0.w + q1.w + q2.w + q3.w;
        float term1 = WM1 / (W1 + 1e-8f);
        float term2 = WM2 / (W2 + 1e-8f);
        float d  = term1 + term2;            // lambda_T - lambda_S
        float ad = fabsf(d);
        float al = (ad < 1.f) ? 0.5f * d * d : ad - 0.5f;

        float a  = warpSum(al);
        float sp = warpSum(__ldcg(g_pos  + tid));
        float sc = warpSum(__ldcg(g_core + tid));
        float sn = warpSum(__ldcg(g_neg  + tid));
        if (lane == 0) {
            s_fr[0][warp] = a;  s_fr[1][warp] = sp;
            s_fr[2][warp] = sc; s_fr[3][warp] = sn;
        }
        __syncthreads();
        if (tid == 0) {
            float A = 0.f, P = 0.f, C = 0.f, Ng = 0.f;
#pragma unroll
            for (int i = 0; i < 8; i++) {
                A += s_fr[0][i]; P += s_fr[1][i];
                C += s_fr[2][i]; Ng += s_fr[3][i];
            }
            out[0] = P / PP + Ng / KK
                   + 0.1f * (C / PP)
                   + 0.1f * (A / PP);
            g_ctr = 0;    // reset for next graph replay
        }
    }
}

// ---------------------------------------------------------------------------
extern "C" void kernel_launch(void* const* d_in, const int* in_sizes, int n_in,
                              void* d_out, int out_size)
{
    const float* z          = (const float*)d_in[0];
    const float* edge_times = (const float*)d_in[1];
    const float* cur_t      = (const float*)d_in[2];
    const float* core       = (const float*)d_in[3];
    const float* omega      = (const float*)d_in[4];
    const float* phi        = (const float*)d_in[5];
    const int*   qidx       = (const int*)d_in[6];
    const int*   neg_idxs   = (const int*)d_in[7];
    const int*   nbr_idxs   = (const int*)d_in[8];
    const int*   neighbors  = (const int*)d_in[9];

    k_all<<<GRID, 256>>>(z, edge_times, cur_t, core, omega, phi,
                         qidx, neg_idxs, nbr_idxs, neighbors, (float*)d_out);
}

// round 6
// speedup vs baseline: 1.0201x; 1.0201x over previous
#include <cuda_runtime.h>

// Shapes fixed by the dataset
#define NN   8192
#define D    128
#define PP   256
#define KK   256
#define DEGN 32
#define FFN  16
#define TEMP_INV (1.0f/0.07f)
#define NB_TERM (PP * 4)          // 4 quarter-blocks per p, 8 warps each
#define NB_NEG  (KK / 8)          // 8 negatives per block, one per warp
#define GRID    (NB_TERM + NB_NEG)

// Scratch (no allocations allowed).  j-major so the tail reduce is coalesced.
__device__ float4 g_part[DEGN * PP];  // [j][p] = {Sw1, Sw1mu1, Sw2, Sw2mu2}
__device__ float  g_pos[PP];
__device__ float  g_core[PP];
__device__ float  g_neg[KK];
__device__ unsigned int g_ctr;        // zero-init; last block resets each launch

__device__ __forceinline__ float warpSum(float v) {
#pragma unroll
    for (int o = 16; o; o >>= 1) v += __shfl_xor_sync(0xffffffffu, v, o);
    return v;
}
// sums independently within each 16-lane half
__device__ __forceinline__ float halfSum(float v) {
#pragma unroll
    for (int o = 8; o; o >>= 1) v += __shfl_xor_sync(0xffffffffu, v, o);
    return v;
}
__device__ __forceinline__ float dot4(float4 a, float4 b) {
    return a.x*b.x + a.y*b.y + a.z*b.z + a.w*b.w;
}
// release-scoped counter increment: orders prior global stores w/o L1 flush
__device__ __forceinline__ unsigned int ctrAddRelease(unsigned int* p) {
    unsigned int old;
    asm volatile("atom.add.release.gpu.global.u32 %0, [%1], 1;"
                 : "=r"(old) : "l"(p) : "memory");
    return old;
}

// ---------------------------------------------------------------------------
// Single fused kernel.  Term blocks (b < NB_TERM): p = b>>2, j = (b&3)*8+warp.
// Each warp is fully self-contained; lane 0 stores its float4 partial directly.
// Neg blocks: one negative per warp.  Last block folds the scalar reduction.
// ---------------------------------------------------------------------------
__global__ void __launch_bounds__(256)
k_all(const float* __restrict__ z,
      const float* __restrict__ edge_times,
      const float* __restrict__ cur_t,
      const float* __restrict__ core,
      const float* __restrict__ omega,
      const float* __restrict__ phi,
      const int*   __restrict__ qidx,
      const int*   __restrict__ neg_idxs,
      const int*   __restrict__ nbr_idxs,
      const int*   __restrict__ neighbors,
      float* __restrict__ out)
{
    __shared__ float s_fr[4][8];
    __shared__ unsigned int s_islast;

    const int tid  = threadIdx.x;
    const int lane = tid & 31, warp = tid >> 5;
    const int b    = blockIdx.x;
    const int q    = qidx[0];            // broadcast load
    const float ct = cur_t[0];

    if (b < NB_TERM) {
        const int p = b >> 2;
        const int j = (b & 3) * 8 + warp;
        const int nbp = nbr_idxs[p];                       // broadcast

        // chain A (depth 2): nqj -> {etq, x};  chain B (depth 3): nbp -> idx2 -> {ety, r}
        const int nqj  = neighbors[q   * DEGN + j];
        const int idx2 = neighbors[nbp * DEGN + j];
        const float etq = edge_times[(size_t)q   * NN + nqj];
        const float ety = edge_times[(size_t)nbp * NN + idx2];

        const float4 x  = ((const float4*)(z + (size_t)nqj  * D))[lane];
        const float4 r  = ((const float4*)(z + (size_t)idx2 * D))[lane];
        const float4 zq = ((const float4*)(z + (size_t)q    * D))[lane];
        const float4 vb = ((const float4*)(z + (size_t)nbp  * D))[lane];

        // time encodings: lanes 0-15 query side, lanes 16-31 neighbor side
        const int   f  = lane & 15;
        const float dt = (lane < 16) ? (ct - etq) : (ct - ety);
        float c = (f == 0) ? (omega[0] * dt + phi[0])
                           : __sinf(omega[f] * dt + phi[f]);

        // independent butterflies (ILP-overlapped)
        float ssx = warpSum(dot4(x, x));
        float ssr = warpSum(dot4(r, r));
        float ssq = warpSum(dot4(zq, zq));
        float ssb = warpSum(dot4(vb, vb));
        float d1  = warpSum(dot4(x, vb));
        float d2  = warpSum(dot4(r, zq));
        float hc  = halfSum(c);
        const float te1 = __shfl_sync(0xffffffffu, hc, 0);
        const float te2 = __shfl_sync(0xffffffffu, hc, 16);

        const float mu1 = 2.f * d1 * rsqrtf(ssx * ssb) - 2.f;
        const float w1  = __expf(mu1 * TEMP_INV - te1);
        const float mu2 = 2.f * d2 * rsqrtf(ssr * ssq) - 2.f;
        const float w2  = __expf(mu2 * TEMP_INV - te2);

        // every lane holds the result; lane 0 stores the warp's partial directly
        if (lane == 0)
            g_part[j * PP + p] = make_float4(w1, w1 * mu1, w2, w2 * mu2);

        // one warp per p additionally emits pos-loss and core term
        if ((b & 3) == 0 && warp == 0) {
            float dqb = warpSum(dot4(vb, zq));
            if (lane == 0) {
                float muxy = 2.f * dqb * rsqrtf(ssb * ssq) - 2.f;
                float sgm  = 1.f / (1.f + __expf(-muxy));
                g_pos[p] = -__logf(sgm + 1e-8f);
                float cd = core[nbp] - core[q];
                g_core[p] = cd * cd;
            }
        }
    } else {
        // negative blocks: warp w handles negative k
        const int k  = (b - NB_TERM) * 8 + warp;
        const int nk = neg_idxs[k];                        // broadcast
        const float4 v  = ((const float4*)(z + (size_t)nk * D))[lane];
        const float4 zq = ((const float4*)(z + (size_t)q  * D))[lane];
        float ssv = warpSum(dot4(v, v));
        float ssq = warpSum(dot4(zq, zq));
        float dv  = warpSum(dot4(v, zq));
        if (lane == 0) {
            float mu  = 2.f * dv * rsqrtf(ssv * ssq) - 2.f;
            float sgm = 1.f / (1.f + __expf(-mu));
            g_neg[k] = -__logf(1.f - sgm + 1e-8f);
        }
    }

    // ---- last-block gate (single barrier before the atomic) ----
    __syncthreads();
    if (tid == 0) {
        unsigned int t = ctrAddRelease(&g_ctr);
        s_islast = (t == (unsigned int)(GRID - 1));
    }
    __syncthreads();
    if (s_islast) {
        // thread tid owns p = tid; j-major layout -> coalesced reads
        float W1 = 0.f, WM1 = 0.f, W2 = 0.f, WM2 = 0.f;
#pragma unroll
        for (int j = 0; j < DEGN; j++) {
            float4 a = __ldcg(&g_part[j * PP + tid]);
            W1 += a.x; WM1 += a.y; W2 += a.z; WM2 += a.w;
        }
        float term1 = WM1 / (W1 + 1e-8f);
        float term2 = WM2 / (W2 + 1e-8f);
        float d  = term1 + term2;            // lambda_T - lambda_S
        float ad = fabsf(d);
        float al = (ad < 1.f) ? 0.5f * d * d : ad - 0.5f;

        float a  = warpSum(al);
        float sp = warpSum(__ldcg(g_pos  + tid));
        float sc = warpSum(__ldcg(g_core + tid));
        float sn = warpSum(__ldcg(g_neg  + tid));
        if (lane == 0) {
            s_fr[0][warp] = a;  s_fr[1][warp] = sp;
            s_fr[2][warp] = sc; s_fr[3][warp] = sn;
        }
        __syncthreads();
        if (tid == 0) {
            float A = 0.f, P = 0.f, C = 0.f, Ng = 0.f;
#pragma unroll
            for (int i = 0; i < 8; i++) {
                A += s_fr[0][i]; P += s_fr[1][i];
                C += s_fr[2][i]; Ng += s_fr[3][i];
            }
            out[0] = P / PP + Ng / KK
                   + 0.1f * (C / PP)
                   + 0.1f * (A / PP);
            g_ctr = 0;    // reset for next graph replay
        }
    }
}

// ---------------------------------------------------------------------------
extern "C" void kernel_launch(void* const* d_in, const int* in_sizes, int n_in,
                              void* d_out, int out_size)
{
    const float* z          = (const float*)d_in[0];
    const float* edge_times = (const float*)d_in[1];
    const float* cur_t      = (const float*)d_in[2];
    const float* core       = (const float*)d_in[3];
    const float* omega      = (const float*)d_in[4];
    const float* phi        = (const float*)d_in[5];
    const int*   qidx       = (const int*)d_in[6];
    const int*   neg_idxs   = (const int*)d_in[7];
    const int*   nbr_idxs   = (const int*)d_in[8];
    const int*   neighbors  = (const int*)d_in[9];

    k_all<<<GRID, 256>>>(z, edge_times, cur_t, core, omega, phi,
                         qidx, neg_idxs, nbr_idxs, neighbors, (float*)d_out);
}